// round 10
// baseline (speedup 1.0000x reference)
#include <cuda_runtime.h>
#include <cuda.h>
#include <cuda_fp16.h>
#include <cstdint>
#include <cstdio>

#define BATCH 8192
#define DIMC  2048
#define KDIM  4096

#define MT 128
#define DT 32              // d-cols per gate per CTA; N_total = 128
#define KCH 64             // k halves per stage (128B rows)
#define NKI (KDIM / KCH)   // 64
#define STG_B 32768        // A 128*128B + B 128*128B
#define EPI_GS 4352        // floats per gate buffer (128*34)
#define BIAS_FO 24576      // float offset of bias (= 3*STG_B/4)
#define SMEM_B 98816       // 3*STG_B + 512

__device__ __half g_Ah[(size_t)BATCH * KDIM];
__device__ __half g_Wh[(size_t)4 * DIMC * KDIM];

__device__ __forceinline__ uint32_t smem_u32(const void* p) {
    uint32_t a;
    asm("{ .reg .u64 t; cvta.to.shared.u64 t, %1; cvt.u32.u64 %0, t; }" : "=r"(a) : "l"(p));
    return a;
}
__device__ __forceinline__ void cpa16(uint32_t s, const void* g) {
    asm volatile("cp.async.cg.shared.global [%0], [%1], 16;" :: "r"(s), "l"(g) : "memory");
}
#define LDM4(r, a) \
    asm volatile("ldmatrix.sync.aligned.m8n8.x4.shared.b16 {%0,%1,%2,%3}, [%4];" \
        : "=r"((r)[0]), "=r"((r)[1]), "=r"((r)[2]), "=r"((r)[3]) : "r"(a))
__device__ __forceinline__ void mma_f16(float* d, const uint32_t* a, const uint32_t* b) {
    asm volatile(
        "mma.sync.aligned.m16n8k16.row.col.f32.f16.f16.f32 "
        "{%0,%1,%2,%3}, {%4,%5,%6,%7}, {%8,%9}, {%0,%1,%2,%3};"
        : "+f"(d[0]), "+f"(d[1]), "+f"(d[2]), "+f"(d[3])
        : "r"(a[0]), "r"(a[1]), "r"(a[2]), "r"(a[3]), "r"(b[0]), "r"(b[1]));
}
__device__ __forceinline__ uint32_t pack2(float a, float b) {
    __half2 h = __floats2half2_rn(a, b);
    return *reinterpret_cast<uint32_t*>(&h);
}

// ---- prep: f32 -> f16 RNE, plain k-order ----
__global__ void prep_A_kernel(const float* __restrict__ x, const float* __restrict__ h) {
    size_t idx = (size_t)blockIdx.x * blockDim.x + threadIdx.x;
    size_t row = idx >> 9; int seg = (int)(idx & 511);
    int cb = seg * 8;
    const float* src = (cb < 2048) ? (x + row * 2048 + cb) : (h + row * 2048 + (cb - 2048));
    float4 v0 = reinterpret_cast<const float4*>(src)[0];
    float4 v1 = reinterpret_cast<const float4*>(src)[1];
    reinterpret_cast<uint4*>(g_Ah)[idx] =
        make_uint4(pack2(v0.x, v0.y), pack2(v0.z, v0.w), pack2(v1.x, v1.y), pack2(v1.z, v1.w));
}
__global__ void prep_W_kernel(const float* __restrict__ wi, const float* __restrict__ wf,
                              const float* __restrict__ wo, const float* __restrict__ wz) {
    size_t idx = (size_t)blockIdx.x * blockDim.x + threadIdx.x;
    size_t j = idx >> 9; int seg = (int)(idx & 511);
    int gate = (int)(j >> 11); size_t r = j & 2047;
    const float* W = (gate == 0) ? wi : (gate == 1) ? wf : (gate == 2) ? wo : wz;
    const float* src = W + r * (size_t)KDIM + seg * 8;
    float4 v0 = reinterpret_cast<const float4*>(src)[0];
    float4 v1 = reinterpret_cast<const float4*>(src)[1];
    reinterpret_cast<uint4*>(g_Wh)[idx] =
        make_uint4(pack2(v0.x, v0.y), pack2(v0.z, v0.w), pack2(v1.x, v1.y), pack2(v1.z, v1.w));
}

// ---- fused GEMM (fp16 in, fp32 acc) + sLSTM ----
__global__ void __launch_bounds__(256, 2)
slstm_gemm(const __half* __restrict__ gA, const __half* __restrict__ gW,
           const float* __restrict__ c_in, const float* __restrict__ n_in,
           const float* __restrict__ m_in,
           const float* __restrict__ bi, const float* __restrict__ bf_,
           const float* __restrict__ bo, const float* __restrict__ bz,
           float* __restrict__ out)
{
    extern __shared__ char smc[];
    float* smf = reinterpret_cast<float*>(smc);
    const int tid = threadIdx.x;
    const int lane = tid & 31, wid = tid >> 5;
    const int wm = wid & 1, wn = wid >> 1;     // M-half, gate

    int bid = blockIdx.x;
    int sg = bid >> 10, r_ = bid & 1023;
    int mt = (sg << 4) + (r_ & 15), dt = r_ >> 4;   // 16 m x 64 d per supergroup
    const int m0 = mt * MT, d0 = dt * DT;

    if (tid < 128) {
        int g = tid >> 5, jj = tid & 31;
        const float* bb = (g == 0) ? bi : (g == 1) ? bf_ : (g == 2) ? bo : bz;
        smf[BIAS_FO + tid] = bb[d0 + jj];
    }
    const uint32_t smb = smem_u32(smc);

    // cp.async base addressing (per-q offsets are compile-time constants):
    // row = row0 + 32q  (row0 = tid>>3 in [0,32), c = tid&7)
    //   A: smem  aSb + q*4096,  gmem aOb + q*32*KDIM (=131072)
    //   B: grow = q*2048 + d0 + row0 -> gmem bOb + q*2048*KDIM (=8388608)
    const int row0 = tid >> 3, ccol = tid & 7;
    const uint32_t aSb = (uint32_t)(row0 * 128 + ((ccol ^ (row0 & 7)) << 4));
    const uint32_t bSb = aSb + 16384u;
    const uint32_t aOb = (uint32_t)((m0 + row0) * KDIM + ccol * 8);
    const uint32_t bOb = (uint32_t)((d0 + row0) * KDIM + ccol * 8);

    // ldmatrix bases: addr = (St + bas) ^ (c<<4); swizzle XOR confined to bits [4:7)
    const int l7 = lane & 7, l3 = (lane >> 3) & 1, l4 = (lane >> 4) & 1;
    uint32_t basA[4], basB[2];
    #pragma unroll
    for (int i = 0; i < 4; ++i) {
        int ra = wm * 64 + i * 16 + l3 * 8 + l7;
        basA[i] = (uint32_t)(ra * 128 + ((ra & 7) << 4));
    }
    #pragma unroll
    for (int j2 = 0; j2 < 2; ++j2) {
        int rb = wn * 32 + j2 * 16 + l4 * 8 + l7;
        basB[j2] = (uint32_t)(16384 + rb * 128 + ((rb & 7) << 4));
    }

    float acc[4][4][4];
    #pragma unroll
    for (int i = 0; i < 4; ++i)
        #pragma unroll
        for (int j = 0; j < 4; ++j)
            #pragma unroll
            for (int t = 0; t < 4; ++t) acc[i][j][t] = 0.0f;

    auto prefetch = [&](int kk) {
        uint32_t base = smb + (kk % 3) * STG_B;
        const __half* ga = gA + aOb + kk * KCH;
        const __half* gb = gW + bOb + kk * KCH;
        #pragma unroll
        for (int q = 0; q < 4; ++q) {
            cpa16(base + aSb + q * 4096u, ga + q * 131072);
            cpa16(base + bSb + q * 4096u, gb + q * 8388608);
        }
        asm volatile("cp.async.commit_group;" ::: "memory");
    };
    auto compute = [&](int st3) {
        const uint32_t St = smb + st3 * STG_B;
        uint32_t bF[2][4];
        // preload s=0 B fragments
        {
            const uint32_t xB = (uint32_t)(l3 << 4);
            LDM4(bF[0], (St + basB[0]) ^ xB);
            LDM4(bF[1], (St + basB[1]) ^ xB);
        }
        #pragma unroll
        for (int s = 0; s < 4; ++s) {
            uint32_t aF[4][4];
            const uint32_t xA = (uint32_t)((2 * s + l4) << 4);
            #pragma unroll
            for (int i = 0; i < 4; ++i)
                LDM4(aF[i], (St + basA[i]) ^ xA);
            uint32_t bCur[2][4];
            #pragma unroll
            for (int j2 = 0; j2 < 2; ++j2)
                #pragma unroll
                for (int t = 0; t < 4; ++t) bCur[j2][t] = bF[j2][t];
            if (s < 3) {   // prefetch next substep's B under the MMA block
                const uint32_t xB = (uint32_t)((2 * (s + 1) + l3) << 4);
                LDM4(bF[0], (St + basB[0]) ^ xB);
                LDM4(bF[1], (St + basB[1]) ^ xB);
            }
            #pragma unroll
            for (int i = 0; i < 4; ++i)
                #pragma unroll
                for (int j2 = 0; j2 < 2; ++j2) {
                    mma_f16(acc[i][2 * j2],     aF[i], &bCur[j2][0]);
                    mma_f16(acc[i][2 * j2 + 1], aF[i], &bCur[j2][2]);
                }
        }
    };

    prefetch(0);
    prefetch(1);

    #pragma unroll 1
    for (int ks = 0; ks < NKI; ++ks) {
        if (ks + 2 < NKI) asm volatile("cp.async.wait_group 1;" ::: "memory");
        else              asm volatile("cp.async.wait_group 0;" ::: "memory");
        __syncthreads();
        if (ks + 2 < NKI) prefetch(ks + 2);
        compute(ks % 3);
    }
    __syncthreads();

    // accums -> per-gate smem
    {
        const int sub = lane >> 2, kl = lane & 3;
        float* sgb = smf + wn * EPI_GS;
        #pragma unroll
        for (int i = 0; i < 4; ++i) {
            int rr = wm * 64 + i * 16 + sub;
            #pragma unroll
            for (int j = 0; j < 4; ++j) {
                int cc = j * 8 + 2 * kl;
                *reinterpret_cast<float2*>(&sgb[rr * 34 + cc]) =
                    make_float2(acc[i][j][0], acc[i][j][1]);
                *reinterpret_cast<float2*>(&sgb[(rr + 8) * 34 + cc]) =
                    make_float2(acc[i][j][2], acc[i][j][3]);
            }
        }
    }
    __syncthreads();

    {
        const int dloc = tid & 31, mb = tid >> 5;   // mb 0..7
        const float bI = smf[BIAS_FO + dloc];
        const float bF2 = smf[BIAS_FO + 32 + dloc];
        const float bO = smf[BIAS_FO + 64 + dloc];
        const float bZ = smf[BIAS_FO + 96 + dloc];
        const size_t PL = (size_t)BATCH * DIMC;
        #pragma unroll 4
        for (int rr = 0; rr < 16; ++rr) {
            int mm = rr * 8 + mb;
            size_t gx = (size_t)(m0 + mm) * DIMC + d0 + dloc;
            float it = smf[0 * EPI_GS + mm * 34 + dloc] + bI;
            float ft = smf[1 * EPI_GS + mm * 34 + dloc] + bF2;
            float ot = smf[2 * EPI_GS + mm * 34 + dloc] + bO;
            float zt = smf[3 * EPI_GS + mm * 34 + dloc] + bZ;
            float cv = c_in[gx], nv = n_in[gx], mv = m_in[gx];
            float z  = tanhf(zt);
            float mn = fmaxf(ft + mv, it);
            float ei = __expf(it - mn);
            float ef = __expf(ft + mv - mn);
            float cn = ef * cv + ei * z;
            float nn2 = ef * nv + ei;
            float sgm = 1.0f / (1.0f + __expf(-ot));
            float hn = sgm * cn / (nn2 + 1e-6f);
            out[gx]          = hn;
            out[PL + gx]     = cn;
            out[2 * PL + gx] = nn2;
            out[3 * PL + gx] = mn;
        }
    }
}

extern "C" void kernel_launch(void* const* d_in, const int* in_sizes, int n_in_cnt,
                              void* d_out, int out_size)
{
    (void)in_sizes; (void)n_in_cnt; (void)out_size;
    const float* x  = (const float*)d_in[0];
    const float* h  = (const float*)d_in[1];
    const float* c  = (const float*)d_in[2];
    const float* nn = (const float*)d_in[3];
    const float* m  = (const float*)d_in[4];
    const float* Wi = (const float*)d_in[5];
    const float* bi = (const float*)d_in[6];
    const float* Wf = (const float*)d_in[7];
    const float* bf = (const float*)d_in[8];
    const float* Wo = (const float*)d_in[9];
    const float* bo = (const float*)d_in[10];
    const float* Wz = (const float*)d_in[11];
    const float* bz = (const float*)d_in[12];
    float* out = (float*)d_out;

    void* pA = nullptr; void* pW = nullptr;
    cudaGetSymbolAddress(&pA, g_Ah);
    cudaGetSymbolAddress(&pW, g_Wh);

    prep_A_kernel<<<16384, 256>>>(x, h);
    prep_W_kernel<<<16384, 256>>>(Wi, Wf, Wo, Wz);

    cudaFuncSetAttribute(slstm_gemm, cudaFuncAttributeMaxDynamicSharedMemorySize, SMEM_B);
    int grid = (BATCH / MT) * (DIMC / DT);   // 4096
    slstm_gemm<<<grid, 256, SMEM_B>>>((const __half*)pA, (const __half*)pW,
                                      c, nn, m, bi, bf, bo, bz, out);
}

// round 11
// speedup vs baseline: 1.2238x; 1.2238x over previous
#include <cuda_runtime.h>
#include <cuda.h>
#include <cuda_fp16.h>
#include <cstdint>
#include <cstdio>

#define BATCH 8192
#define DIMC  2048
#define KDIM  4096

#define MT 128
#define DT 32              // d-cols per gate per CTA; N_total = 128
#define KCH 64             // k halves per stage (128B rows)
#define NKI (KDIM / KCH)   // 64
#define STG_B 32768        // A 128*128B + B 128*128B
#define EPI_GS 4352        // floats per gate buffer (128*34)
#define BIAS_FO 24576      // float offset of bias (= 3*STG_B/4)
#define SMEM_B 98816       // 3*STG_B + 512

__device__ __half g_Ah[(size_t)BATCH * KDIM];
__device__ __half g_Wh[(size_t)4 * DIMC * KDIM];

__device__ __forceinline__ uint32_t smem_u32(const void* p) {
    uint32_t a;
    asm("{ .reg .u64 t; cvta.to.shared.u64 t, %1; cvt.u32.u64 %0, t; }" : "=r"(a) : "l"(p));
    return a;
}
__device__ __forceinline__ void cpa16(uint32_t s, const void* g) {
    asm volatile("cp.async.cg.shared.global [%0], [%1], 16;" :: "r"(s), "l"(g) : "memory");
}
#define LDM4(r, a) \
    asm volatile("ldmatrix.sync.aligned.m8n8.x4.shared.b16 {%0,%1,%2,%3}, [%4];" \
        : "=r"((r)[0]), "=r"((r)[1]), "=r"((r)[2]), "=r"((r)[3]) : "r"(a))
__device__ __forceinline__ void mma_f16(float* d, const uint32_t* a, const uint32_t* b) {
    asm volatile(
        "mma.sync.aligned.m16n8k16.row.col.f32.f16.f16.f32 "
        "{%0,%1,%2,%3}, {%4,%5,%6,%7}, {%8,%9}, {%0,%1,%2,%3};"
        : "+f"(d[0]), "+f"(d[1]), "+f"(d[2]), "+f"(d[3])
        : "r"(a[0]), "r"(a[1]), "r"(a[2]), "r"(a[3]), "r"(b[0]), "r"(b[1]));
}
__device__ __forceinline__ uint32_t pack2(float a, float b) {
    __half2 h = __floats2half2_rn(a, b);
    return *reinterpret_cast<uint32_t*>(&h);
}

// ---- prep: f32 -> f16 RNE, plain k-order ----
__global__ void prep_A_kernel(const float* __restrict__ x, const float* __restrict__ h) {
    size_t idx = (size_t)blockIdx.x * blockDim.x + threadIdx.x;
    size_t row = idx >> 9; int seg = (int)(idx & 511);
    int cb = seg * 8;
    const float* src = (cb < 2048) ? (x + row * 2048 + cb) : (h + row * 2048 + (cb - 2048));
    float4 v0 = reinterpret_cast<const float4*>(src)[0];
    float4 v1 = reinterpret_cast<const float4*>(src)[1];
    reinterpret_cast<uint4*>(g_Ah)[idx] =
        make_uint4(pack2(v0.x, v0.y), pack2(v0.z, v0.w), pack2(v1.x, v1.y), pack2(v1.z, v1.w));
}
__global__ void prep_W_kernel(const float* __restrict__ wi, const float* __restrict__ wf,
                              const float* __restrict__ wo, const float* __restrict__ wz) {
    size_t idx = (size_t)blockIdx.x * blockDim.x + threadIdx.x;
    size_t j = idx >> 9; int seg = (int)(idx & 511);
    int gate = (int)(j >> 11); size_t r = j & 2047;
    const float* W = (gate == 0) ? wi : (gate == 1) ? wf : (gate == 2) ? wo : wz;
    const float* src = W + r * (size_t)KDIM + seg * 8;
    float4 v0 = reinterpret_cast<const float4*>(src)[0];
    float4 v1 = reinterpret_cast<const float4*>(src)[1];
    reinterpret_cast<uint4*>(g_Wh)[idx] =
        make_uint4(pack2(v0.x, v0.y), pack2(v0.z, v0.w), pack2(v1.x, v1.y), pack2(v1.z, v1.w));
}

// ---- fused GEMM (fp16 in, fp32 acc) + sLSTM ----
__global__ void __launch_bounds__(256, 2)
slstm_gemm(const __half* __restrict__ gA, const __half* __restrict__ gW,
           const float* __restrict__ c_in, const float* __restrict__ n_in,
           const float* __restrict__ m_in,
           const float* __restrict__ bi, const float* __restrict__ bf_,
           const float* __restrict__ bo, const float* __restrict__ bz,
           float* __restrict__ out)
{
    extern __shared__ char smc[];
    float* smf = reinterpret_cast<float*>(smc);
    const int tid = threadIdx.x;
    const int lane = tid & 31, wid = tid >> 5;
    const int wm = wid & 1, wn = wid >> 1;     // M-half, gate

    int bid = blockIdx.x;
    int sg = bid >> 10, r_ = bid & 1023;
    int mt = (sg << 4) + (r_ & 15), dt = r_ >> 4;   // 16 m x 64 d per supergroup
    const int m0 = mt * MT, d0 = dt * DT;

    if (tid < 128) {
        int g = tid >> 5, jj = tid & 31;
        const float* bb = (g == 0) ? bi : (g == 1) ? bf_ : (g == 2) ? bo : bz;
        smf[BIAS_FO + tid] = bb[d0 + jj];
    }
    const uint32_t smb = smem_u32(smc);

    // cp.async: A 1024 chunks (4/thr), B 1024 chunks (4/thr)
    uint32_t aS[4], aO[4], bS[4], bO[4];
    #pragma unroll
    for (int q = 0; q < 4; ++q) {
        int id = tid + q * 256, row = id >> 3, c = id & 7;
        aS[q] = (uint32_t)(row * 128 + ((c ^ (row & 7)) << 4));
        aO[q] = (uint32_t)((m0 + row) * KDIM + c * 8);
        int grow = ((row >> 5) << 11) + d0 + (row & 31);
        bS[q] = (uint32_t)(16384 + row * 128 + ((c ^ (row & 7)) << 4));
        bO[q] = (uint32_t)(grow * KDIM + c * 8);
    }

    // ldmatrix bases: addr = (St + bas) ^ (c<<4); swizzle XOR confined to bits [4:7)
    const int l7 = lane & 7, l3 = (lane >> 3) & 1, l4 = (lane >> 4) & 1;
    uint32_t basA[4], basB[2];
    #pragma unroll
    for (int i = 0; i < 4; ++i) {
        int ra = wm * 64 + i * 16 + l3 * 8 + l7;
        basA[i] = (uint32_t)(ra * 128 + ((ra & 7) << 4));
    }
    #pragma unroll
    for (int j2 = 0; j2 < 2; ++j2) {
        int rb = wn * 32 + j2 * 16 + l4 * 8 + l7;
        basB[j2] = (uint32_t)(16384 + rb * 128 + ((rb & 7) << 4));
    }

    float acc[4][4][4];
    #pragma unroll
    for (int i = 0; i < 4; ++i)
        #pragma unroll
        for (int j = 0; j < 4; ++j)
            #pragma unroll
            for (int t = 0; t < 4; ++t) acc[i][j][t] = 0.0f;

    #pragma unroll
    for (int p = 0; p < 2; ++p) {
        uint32_t base = smb + p * STG_B;
        int ko = p * KCH;
        #pragma unroll
        for (int q = 0; q < 4; ++q) { cpa16(base + aS[q], gA + aO[q] + ko);
                                      cpa16(base + bS[q], gW + bO[q] + ko); }
        asm volatile("cp.async.commit_group;" ::: "memory");
    }

    #pragma unroll 3
    for (int ks = 0; ks < NKI; ++ks) {
        if (ks + 2 < NKI) asm volatile("cp.async.wait_group 1;" ::: "memory");
        else              asm volatile("cp.async.wait_group 0;" ::: "memory");
        __syncthreads();

        if (ks + 2 < NKI) {
            uint32_t base = smb + ((ks + 2) % 3) * STG_B;
            int ko = (ks + 2) * KCH;
            #pragma unroll
            for (int q = 0; q < 4; ++q) { cpa16(base + aS[q], gA + aO[q] + ko);
                                          cpa16(base + bS[q], gW + bO[q] + ko); }
            asm volatile("cp.async.commit_group;" ::: "memory");
        }

        const uint32_t St = smb + (ks % 3) * STG_B;
        #pragma unroll
        for (int s = 0; s < 4; ++s) {
            uint32_t aF[4][4], bF[2][4];
            const uint32_t xA = (uint32_t)((2 * s + l4) << 4);
            const uint32_t xB = (uint32_t)((2 * s + l3) << 4);
            #pragma unroll
            for (int j2 = 0; j2 < 2; ++j2)
                LDM4(bF[j2], (St + basB[j2]) ^ xB);
            #pragma unroll
            for (int i = 0; i < 4; ++i)
                LDM4(aF[i], (St + basA[i]) ^ xA);
            #pragma unroll
            for (int i = 0; i < 4; ++i)
                #pragma unroll
                for (int j2 = 0; j2 < 2; ++j2) {
                    mma_f16(acc[i][2 * j2],     aF[i], &bF[j2][0]);
                    mma_f16(acc[i][2 * j2 + 1], aF[i], &bF[j2][2]);
                }
        }
    }
    __syncthreads();

    // accums -> per-gate smem
    {
        const int sub = lane >> 2, kl = lane & 3;
        float* sgb = smf + wn * EPI_GS;
        #pragma unroll
        for (int i = 0; i < 4; ++i) {
            int rr = wm * 64 + i * 16 + sub;
            #pragma unroll
            for (int j = 0; j < 4; ++j) {
                int cc = j * 8 + 2 * kl;
                *reinterpret_cast<float2*>(&sgb[rr * 34 + cc]) =
                    make_float2(acc[i][j][0], acc[i][j][1]);
                *reinterpret_cast<float2*>(&sgb[(rr + 8) * 34 + cc]) =
                    make_float2(acc[i][j][2], acc[i][j][3]);
            }
        }
    }
    __syncthreads();

    {
        const int dloc = tid & 31, mb = tid >> 5;   // mb 0..7
        const float bI = smf[BIAS_FO + dloc];
        const float bF = smf[BIAS_FO + 32 + dloc];
        const float bO = smf[BIAS_FO + 64 + dloc];
        const float bZ = smf[BIAS_FO + 96 + dloc];
        const size_t PL = (size_t)BATCH * DIMC;
        #pragma unroll 4
        for (int rr = 0; rr < 16; ++rr) {
            int mm = rr * 8 + mb;
            size_t gx = (size_t)(m0 + mm) * DIMC + d0 + dloc;
            float it = smf[0 * EPI_GS + mm * 34 + dloc] + bI;
            float ft = smf[1 * EPI_GS + mm * 34 + dloc] + bF;
            float ot = smf[2 * EPI_GS + mm * 34 + dloc] + bO;
            float zt = smf[3 * EPI_GS + mm * 34 + dloc] + bZ;
            float cv = c_in[gx], nv = n_in[gx], mv = m_in[gx];
            float z  = tanhf(zt);
            float mn = fmaxf(ft + mv, it);
            float ei = __expf(it - mn);
            float ef = __expf(ft + mv - mn);
            float cn = ef * cv + ei * z;
            float nn2 = ef * nv + ei;
            float sgm = 1.0f / (1.0f + __expf(-ot));
            float hn = sgm * cn / (nn2 + 1e-6f);
            out[gx]          = hn;
            out[PL + gx]     = cn;
            out[2 * PL + gx] = nn2;
            out[3 * PL + gx] = mn;
        }
    }
}

extern "C" void kernel_launch(void* const* d_in, const int* in_sizes, int n_in_cnt,
                              void* d_out, int out_size)
{
    (void)in_sizes; (void)n_in_cnt; (void)out_size;
    const float* x  = (const float*)d_in[0];
    const float* h  = (const float*)d_in[1];
    const float* c  = (const float*)d_in[2];
    const float* nn = (const float*)d_in[3];
    const float* m  = (const float*)d_in[4];
    const float* Wi = (const float*)d_in[5];
    const float* bi = (const float*)d_in[6];
    const float* Wf = (const float*)d_in[7];
    const float* bf = (const float*)d_in[8];
    const float* Wo = (const float*)d_in[9];
    const float* bo = (const float*)d_in[10];
    const float* Wz = (const float*)d_in[11];
    const float* bz = (const float*)d_in[12];
    float* out = (float*)d_out;

    void* pA = nullptr; void* pW = nullptr;
    cudaGetSymbolAddress(&pA, g_Ah);
    cudaGetSymbolAddress(&pW, g_Wh);

    prep_A_kernel<<<16384, 256>>>(x, h);
    prep_W_kernel<<<16384, 256>>>(Wi, Wf, Wo, Wz);

    cudaFuncSetAttribute(slstm_gemm, cudaFuncAttributeMaxDynamicSharedMemorySize, SMEM_B);
    int grid = (BATCH / MT) * (DIMC / DT);   // 4096
    slstm_gemm<<<grid, 256, SMEM_B>>>((const __half*)pA, (const __half*)pW,
                                      c, nn, m, bi, bf, bo, bz, out);
}

// round 12
// speedup vs baseline: 1.5284x; 1.2489x over previous
#include <cuda_runtime.h>
#include <cuda.h>
#include <cuda_fp16.h>
#include <cstdint>
#include <cstdio>

#define BATCH 8192
#define DIMC  2048
#define KDIM  4096

#define MT 128
#define DT 32              // d-cols per gate per CTA; N_total = 128
#define KCH 64             // k halves per stage (128B rows)
#define NKI (KDIM / KCH)   // 64
#define STG_B 32768        // A 128*128B + B 128*128B
#define EPI_GS 4352        // floats per gate buffer (128*34)
#define BIAS_FO 24576      // float offset of bias (= 3*STG_B/4)
#define SMEM_B 98816       // 3*STG_B + 512

__device__ __half g_Ah[(size_t)BATCH * KDIM];
__device__ __half g_Wh[(size_t)4 * DIMC * KDIM];

__device__ __forceinline__ uint32_t smem_u32(const void* p) {
    uint32_t a;
    asm("{ .reg .u64 t; cvta.to.shared.u64 t, %1; cvt.u32.u64 %0, t; }" : "=r"(a) : "l"(p));
    return a;
}
__device__ __forceinline__ void cpa16(uint32_t s, const void* g) {
    asm volatile("cp.async.cg.shared.global [%0], [%1], 16;" :: "r"(s), "l"(g) : "memory");
}
#define LDM4(r, a) \
    asm volatile("ldmatrix.sync.aligned.m8n8.x4.shared.b16 {%0,%1,%2,%3}, [%4];" \
        : "=r"((r)[0]), "=r"((r)[1]), "=r"((r)[2]), "=r"((r)[3]) : "r"(a))
__device__ __forceinline__ void mma_f16(float* d, const uint32_t* a, const uint32_t* b) {
    asm volatile(
        "mma.sync.aligned.m16n8k16.row.col.f32.f16.f16.f32 "
        "{%0,%1,%2,%3}, {%4,%5,%6,%7}, {%8,%9}, {%0,%1,%2,%3};"
        : "+f"(d[0]), "+f"(d[1]), "+f"(d[2]), "+f"(d[3])
        : "r"(a[0]), "r"(a[1]), "r"(a[2]), "r"(a[3]), "r"(b[0]), "r"(b[1]));
}
__device__ __forceinline__ uint32_t pack2(float a, float b) {
    __half2 h = __floats2half2_rn(a, b);
    return *reinterpret_cast<uint32_t*>(&h);
}

// ---- prep: f32 -> f16 RNE, plain k-order ----
__global__ void prep_A_kernel(const float* __restrict__ x, const float* __restrict__ h) {
    size_t idx = (size_t)blockIdx.x * blockDim.x + threadIdx.x;
    size_t row = idx >> 9; int seg = (int)(idx & 511);
    int cb = seg * 8;
    const float* src = (cb < 2048) ? (x + row * 2048 + cb) : (h + row * 2048 + (cb - 2048));
    float4 v0 = reinterpret_cast<const float4*>(src)[0];
    float4 v1 = reinterpret_cast<const float4*>(src)[1];
    reinterpret_cast<uint4*>(g_Ah)[idx] =
        make_uint4(pack2(v0.x, v0.y), pack2(v0.z, v0.w), pack2(v1.x, v1.y), pack2(v1.z, v1.w));
}
__global__ void prep_W_kernel(const float* __restrict__ wi, const float* __restrict__ wf,
                              const float* __restrict__ wo, const float* __restrict__ wz) {
    size_t idx = (size_t)blockIdx.x * blockDim.x + threadIdx.x;
    size_t j = idx >> 9; int seg = (int)(idx & 511);
    int gate = (int)(j >> 11); size_t r = j & 2047;
    const float* W = (gate == 0) ? wi : (gate == 1) ? wf : (gate == 2) ? wo : wz;
    const float* src = W + r * (size_t)KDIM + seg * 8;
    float4 v0 = reinterpret_cast<const float4*>(src)[0];
    float4 v1 = reinterpret_cast<const float4*>(src)[1];
    reinterpret_cast<uint4*>(g_Wh)[idx] =
        make_uint4(pack2(v0.x, v0.y), pack2(v0.z, v0.w), pack2(v1.x, v1.y), pack2(v1.z, v1.w));
}

// ---- fused GEMM (fp16 in, fp32 acc) + sLSTM ----
__global__ void __launch_bounds__(256, 2)
slstm_gemm(const __half* __restrict__ gA, const __half* __restrict__ gW,
           const float* __restrict__ c_in, const float* __restrict__ n_in,
           const float* __restrict__ m_in,
           const float* __restrict__ bi, const float* __restrict__ bf_,
           const float* __restrict__ bo, const float* __restrict__ bz,
           float* __restrict__ out)
{
    extern __shared__ char smc[];
    float* smf = reinterpret_cast<float*>(smc);
    const int tid = threadIdx.x;
    const int lane = tid & 31, wid = tid >> 5;
    const int wm = wid & 1, wn = wid >> 1;     // M-half, gate

    int bid = blockIdx.x;
    int sg = bid >> 10, r_ = bid & 1023;
    int mt = (sg << 4) + (r_ & 15), dt = r_ >> 4;   // 16 m x 64 d per supergroup
    const int m0 = mt * MT, d0 = dt * DT;

    if (tid < 128) {
        int g = tid >> 5, jj = tid & 31;
        const float* bb = (g == 0) ? bi : (g == 1) ? bf_ : (g == 2) ? bo : bz;
        smf[BIAS_FO + tid] = bb[d0 + jj];
    }
    const uint32_t smb = smem_u32(smc);

    // cp.async: A 1024 chunks (4/thr), B 1024 chunks (4/thr)
    uint32_t aS[4], aO[4], bS[4], bO[4];
    #pragma unroll
    for (int q = 0; q < 4; ++q) {
        int id = tid + q * 256, row = id >> 3, c = id & 7;
        aS[q] = (uint32_t)(row * 128 + ((c ^ (row & 7)) << 4));
        aO[q] = (uint32_t)((m0 + row) * KDIM + c * 8);
        int grow = ((row >> 5) << 11) + d0 + (row & 31);
        bS[q] = (uint32_t)(16384 + row * 128 + ((c ^ (row & 7)) << 4));
        bO[q] = (uint32_t)(grow * KDIM + c * 8);
    }

    // ldmatrix bases: addr = (St + bas) ^ (c<<4); swizzle XOR confined to bits [4:7)
    const int l7 = lane & 7, l3 = (lane >> 3) & 1, l4 = (lane >> 4) & 1;
    uint32_t basA[4], basB[2];
    #pragma unroll
    for (int i = 0; i < 4; ++i) {
        int ra = wm * 64 + i * 16 + l3 * 8 + l7;
        basA[i] = (uint32_t)(ra * 128 + ((ra & 7) << 4));
    }
    #pragma unroll
    for (int j2 = 0; j2 < 2; ++j2) {
        int rb = wn * 32 + j2 * 16 + l4 * 8 + l7;
        basB[j2] = (uint32_t)(16384 + rb * 128 + ((rb & 7) << 4));
    }

    float acc[4][4][4];
    #pragma unroll
    for (int i = 0; i < 4; ++i)
        #pragma unroll
        for (int j = 0; j < 4; ++j)
            #pragma unroll
            for (int t = 0; t < 4; ++t) acc[i][j][t] = 0.0f;

    #pragma unroll
    for (int p = 0; p < 2; ++p) {
        uint32_t base = smb + p * STG_B;
        int ko = p * KCH;
        #pragma unroll
        for (int q = 0; q < 4; ++q) { cpa16(base + aS[q], gA + aO[q] + ko);
                                      cpa16(base + bS[q], gW + bO[q] + ko); }
        asm volatile("cp.async.commit_group;" ::: "memory");
    }

    for (int ks = 0; ks < NKI; ++ks) {
        if (ks + 2 < NKI) asm volatile("cp.async.wait_group 1;" ::: "memory");
        else              asm volatile("cp.async.wait_group 0;" ::: "memory");
        __syncthreads();

        if (ks + 2 < NKI) {
            uint32_t base = smb + ((ks + 2) % 3) * STG_B;
            int ko = (ks + 2) * KCH;
            #pragma unroll
            for (int q = 0; q < 4; ++q) { cpa16(base + aS[q], gA + aO[q] + ko);
                                          cpa16(base + bS[q], gW + bO[q] + ko); }
            asm volatile("cp.async.commit_group;" ::: "memory");
        }

        const uint32_t St = smb + (ks % 3) * STG_B;
        #pragma unroll
        for (int s = 0; s < 4; ++s) {
            uint32_t aF[4][4], bF[2][4];
            const uint32_t xA = (uint32_t)((2 * s + l4) << 4);
            const uint32_t xB = (uint32_t)((2 * s + l3) << 4);
            #pragma unroll
            for (int j2 = 0; j2 < 2; ++j2)
                LDM4(bF[j2], (St + basB[j2]) ^ xB);
            #pragma unroll
            for (int i = 0; i < 4; ++i)
                LDM4(aF[i], (St + basA[i]) ^ xA);
            #pragma unroll
            for (int i = 0; i < 4; ++i)
                #pragma unroll
                for (int j2 = 0; j2 < 2; ++j2) {
                    mma_f16(acc[i][2 * j2],     aF[i], &bF[j2][0]);
                    mma_f16(acc[i][2 * j2 + 1], aF[i], &bF[j2][2]);
                }
        }
    }
    __syncthreads();

    // accums -> per-gate smem
    {
        const int sub = lane >> 2, kl = lane & 3;
        float* sgb = smf + wn * EPI_GS;
        #pragma unroll
        for (int i = 0; i < 4; ++i) {
            int rr = wm * 64 + i * 16 + sub;
            #pragma unroll
            for (int j = 0; j < 4; ++j) {
                int cc = j * 8 + 2 * kl;
                *reinterpret_cast<float2*>(&sgb[rr * 34 + cc]) =
                    make_float2(acc[i][j][0], acc[i][j][1]);
                *reinterpret_cast<float2*>(&sgb[(rr + 8) * 34 + cc]) =
                    make_float2(acc[i][j][2], acc[i][j][3]);
            }
        }
    }
    __syncthreads();

    {
        const int dloc = tid & 31, mb = tid >> 5;   // mb 0..7
        const float bI = smf[BIAS_FO + dloc];
        const float bF = smf[BIAS_FO + 32 + dloc];
        const float bO = smf[BIAS_FO + 64 + dloc];
        const float bZ = smf[BIAS_FO + 96 + dloc];
        const size_t PL = (size_t)BATCH * DIMC;
        #pragma unroll 4
        for (int rr = 0; rr < 16; ++rr) {
            int mm = rr * 8 + mb;
            size_t gx = (size_t)(m0 + mm) * DIMC + d0 + dloc;
            float it = smf[0 * EPI_GS + mm * 34 + dloc] + bI;
            float ft = smf[1 * EPI_GS + mm * 34 + dloc] + bF;
            float ot = smf[2 * EPI_GS + mm * 34 + dloc] + bO;
            float zt = smf[3 * EPI_GS + mm * 34 + dloc] + bZ;
            float cv = c_in[gx], nv = n_in[gx], mv = m_in[gx];
            float z  = tanhf(zt);
            float mn = fmaxf(ft + mv, it);
            float ei = __expf(it - mn);
            float ef = __expf(ft + mv - mn);
            float cn = ef * cv + ei * z;
            float nn2 = ef * nv + ei;
            float sgm = 1.0f / (1.0f + __expf(-ot));
            float hn = sgm * cn / (nn2 + 1e-6f);
            out[gx]          = hn;
            out[PL + gx]     = cn;
            out[2 * PL + gx] = nn2;
            out[3 * PL + gx] = mn;
        }
    }
}

extern "C" void kernel_launch(void* const* d_in, const int* in_sizes, int n_in_cnt,
                              void* d_out, int out_size)
{
    (void)in_sizes; (void)n_in_cnt; (void)out_size;
    const float* x  = (const float*)d_in[0];
    const float* h  = (const float*)d_in[1];
    const float* c  = (const float*)d_in[2];
    const float* nn = (const float*)d_in[3];
    const float* m  = (const float*)d_in[4];
    const float* Wi = (const float*)d_in[5];
    const float* bi = (const float*)d_in[6];
    const float* Wf = (const float*)d_in[7];
    const float* bf = (const float*)d_in[8];
    const float* Wo = (const float*)d_in[9];
    const float* bo = (const float*)d_in[10];
    const float* Wz = (const float*)d_in[11];
    const float* bz = (const float*)d_in[12];
    float* out = (float*)d_out;

    void* pA = nullptr; void* pW = nullptr;
    cudaGetSymbolAddress(&pA, g_Ah);
    cudaGetSymbolAddress(&pW, g_Wh);

    prep_A_kernel<<<16384, 256>>>(x, h);
    prep_W_kernel<<<16384, 256>>>(Wi, Wf, Wo, Wz);

    cudaFuncSetAttribute(slstm_gemm, cudaFuncAttributeMaxDynamicSharedMemorySize, SMEM_B);
    int grid = (BATCH / MT) * (DIMC / DT);   // 4096
    slstm_gemm<<<grid, 256, SMEM_B>>>((const __half*)pA, (const __half*)pW,
                                      c, nn, m, bi, bf, bo, bz, out);
}

// round 13
// speedup vs baseline: 1.5795x; 1.0334x over previous
#include <cuda_runtime.h>
#include <cuda.h>
#include <cuda_fp16.h>
#include <cstdint>
#include <cstdio>

#define BATCH 8192
#define DIMC  2048
#define KDIM  4096

#define MT 128
#define DT 32              // d-cols per gate per CTA; N_total = 128
#define KCH 64             // k halves per stage (128B rows)
#define NKI (KDIM / KCH)   // 64
#define STG_B 32768        // A 128*128B + B 128*128B
#define EPI_GS 4352        // floats per gate buffer (128*34)
#define BIAS_FO 24576      // float offset of bias (= 3*STG_B/4)
#define MB_OFF 98816       // byte offset of mbarriers (after bias)
#define SMEM_B 98880       // 3*STG_B + 512 + 64 (mbarriers)

__device__ __half g_Ah[(size_t)BATCH * KDIM];
__device__ __half g_Wh[(size_t)4 * DIMC * KDIM];

__device__ __forceinline__ uint32_t smem_u32(const void* p) {
    uint32_t a;
    asm("{ .reg .u64 t; cvta.to.shared.u64 t, %1; cvt.u32.u64 %0, t; }" : "=r"(a) : "l"(p));
    return a;
}
__device__ __forceinline__ void cpa16(uint32_t s, const void* g) {
    asm volatile("cp.async.cg.shared.global [%0], [%1], 16;" :: "r"(s), "l"(g) : "memory");
}
#define LDM4(r, a) \
    asm volatile("ldmatrix.sync.aligned.m8n8.x4.shared.b16 {%0,%1,%2,%3}, [%4];" \
        : "=r"((r)[0]), "=r"((r)[1]), "=r"((r)[2]), "=r"((r)[3]) : "r"(a))
__device__ __forceinline__ void mma_f16(float* d, const uint32_t* a, const uint32_t* b) {
    asm volatile(
        "mma.sync.aligned.m16n8k16.row.col.f32.f16.f16.f32 "
        "{%0,%1,%2,%3}, {%4,%5,%6,%7}, {%8,%9}, {%0,%1,%2,%3};"
        : "+f"(d[0]), "+f"(d[1]), "+f"(d[2]), "+f"(d[3])
        : "r"(a[0]), "r"(a[1]), "r"(a[2]), "r"(a[3]), "r"(b[0]), "r"(b[1]));
}
__device__ __forceinline__ uint32_t pack2(float a, float b) {
    __half2 h = __floats2half2_rn(a, b);
    return *reinterpret_cast<uint32_t*>(&h);
}

#define MBAR_INIT(a, c) \
    asm volatile("mbarrier.init.shared.b64 [%0], %1;" :: "r"((uint32_t)(a)), "r"((uint32_t)(c)) : "memory")
#define MBAR_ARRIVE(a) \
    asm volatile("mbarrier.arrive.shared.b64 _, [%0];" :: "r"((uint32_t)(a)) : "memory")
#define CPA_ARRIVE(a) \
    asm volatile("cp.async.mbarrier.arrive.noinc.shared.b64 [%0];" :: "r"((uint32_t)(a)) : "memory")
#define MBAR_WAIT(a, p) do { \
    uint32_t _mb = (uint32_t)(a), _pa = (uint32_t)(p), _dn; \
    asm volatile("{\n\t.reg .pred q;\n\tmbarrier.try_wait.parity.acquire.cta.shared::cta.b64 q, [%1], %2;\n\tselp.b32 %0,1,0,q;\n\t}" \
        : "=r"(_dn) : "r"(_mb), "r"(_pa) : "memory"); \
    if (!_dn) { \
        asm volatile("{\n\t.reg .pred Q;\n\tWL_%=:\n\tmbarrier.try_wait.parity.acquire.cta.shared::cta.b64 Q, [%0], %1, 0x989680;\n\t@Q bra.uni WD_%=;\n\tbra.uni WL_%=;\n\tWD_%=:\n\t}" \
            :: "r"(_mb), "r"(_pa) : "memory"); \
    } \
} while (0)

// ---- prep: f32 -> f16 RNE, plain k-order ----
__global__ void prep_A_kernel(const float* __restrict__ x, const float* __restrict__ h) {
    size_t idx = (size_t)blockIdx.x * blockDim.x + threadIdx.x;
    size_t row = idx >> 9; int seg = (int)(idx & 511);
    int cb = seg * 8;
    const float* src = (cb < 2048) ? (x + row * 2048 + cb) : (h + row * 2048 + (cb - 2048));
    float4 v0 = reinterpret_cast<const float4*>(src)[0];
    float4 v1 = reinterpret_cast<const float4*>(src)[1];
    reinterpret_cast<uint4*>(g_Ah)[idx] =
        make_uint4(pack2(v0.x, v0.y), pack2(v0.z, v0.w), pack2(v1.x, v1.y), pack2(v1.z, v1.w));
}
__global__ void prep_W_kernel(const float* __restrict__ wi, const float* __restrict__ wf,
                              const float* __restrict__ wo, const float* __restrict__ wz) {
    size_t idx = (size_t)blockIdx.x * blockDim.x + threadIdx.x;
    size_t j = idx >> 9; int seg = (int)(idx & 511);
    int gate = (int)(j >> 11); size_t r = j & 2047;
    const float* W = (gate == 0) ? wi : (gate == 1) ? wf : (gate == 2) ? wo : wz;
    const float* src = W + r * (size_t)KDIM + seg * 8;
    float4 v0 = reinterpret_cast<const float4*>(src)[0];
    float4 v1 = reinterpret_cast<const float4*>(src)[1];
    reinterpret_cast<uint4*>(g_Wh)[idx] =
        make_uint4(pack2(v0.x, v0.y), pack2(v0.z, v0.w), pack2(v1.x, v1.y), pack2(v1.z, v1.w));
}

// ---- fused GEMM (fp16 in, fp32 acc) + sLSTM; mbarrier-decoupled pipeline ----
__global__ void __launch_bounds__(256, 2)
slstm_gemm(const __half* __restrict__ gA, const __half* __restrict__ gW,
           const float* __restrict__ c_in, const float* __restrict__ n_in,
           const float* __restrict__ m_in,
           const float* __restrict__ bi, const float* __restrict__ bf_,
           const float* __restrict__ bo, const float* __restrict__ bz,
           float* __restrict__ out)
{
    extern __shared__ char smc[];
    float* smf = reinterpret_cast<float*>(smc);
    const int tid = threadIdx.x;
    const int lane = tid & 31, wid = tid >> 5;
    const int wm = wid & 1, wn = wid >> 1;     // M-half, gate

    int bid = blockIdx.x;
    int sg = bid >> 10, r_ = bid & 1023;
    int mt = (sg << 4) + (r_ & 15), dt = r_ >> 4;   // 16 m x 64 d per supergroup
    const int m0 = mt * MT, d0 = dt * DT;

    if (tid < 128) {
        int g = tid >> 5, jj = tid & 31;
        const float* bb = (g == 0) ? bi : (g == 1) ? bf_ : (g == 2) ? bo : bz;
        smf[BIAS_FO + tid] = bb[d0 + jj];
    }
    const uint32_t smb = smem_u32(smc);

    // mbarriers: full[3] at MB_OFF (count 256), free[3] at MB_OFF+24 (count 8)
    if (tid < 3) {
        MBAR_INIT(smb + MB_OFF + tid * 8, 256);
        MBAR_INIT(smb + MB_OFF + 24 + tid * 8, 8);
    }

    // cp.async: A 1024 chunks (4/thr), B 1024 chunks (4/thr)
    uint32_t aS[4], aO[4], bS[4], bO[4];
    #pragma unroll
    for (int q = 0; q < 4; ++q) {
        int id = tid + q * 256, row = id >> 3, c = id & 7;
        aS[q] = (uint32_t)(row * 128 + ((c ^ (row & 7)) << 4));
        aO[q] = (uint32_t)((m0 + row) * KDIM + c * 8);
        int grow = ((row >> 5) << 11) + d0 + (row & 31);
        bS[q] = (uint32_t)(16384 + row * 128 + ((c ^ (row & 7)) << 4));
        bO[q] = (uint32_t)(grow * KDIM + c * 8);
    }

    // ldmatrix bases: addr = (St + bas) ^ (c<<4); swizzle XOR confined to bits [4:7)
    const int l7 = lane & 7, l3 = (lane >> 3) & 1, l4 = (lane >> 4) & 1;
    uint32_t basA[4], basB[2];
    #pragma unroll
    for (int i = 0; i < 4; ++i) {
        int ra = wm * 64 + i * 16 + l3 * 8 + l7;
        basA[i] = (uint32_t)(ra * 128 + ((ra & 7) << 4));
    }
    #pragma unroll
    for (int j2 = 0; j2 < 2; ++j2) {
        int rb = wn * 32 + j2 * 16 + l4 * 8 + l7;
        basB[j2] = (uint32_t)(16384 + rb * 128 + ((rb & 7) << 4));
    }

    float acc[4][4][4];
    #pragma unroll
    for (int i = 0; i < 4; ++i)
        #pragma unroll
        for (int j = 0; j < 4; ++j)
            #pragma unroll
            for (int t = 0; t < 4; ++t) acc[i][j][t] = 0.0f;

    __syncthreads();   // mbarrier init + bias visible before any cp.async/compute

    auto prefetch = [&](int kk) {
        int st = kk % 3;
        uint32_t base = smb + st * STG_B;
        int ko = kk * KCH;
        #pragma unroll
        for (int q = 0; q < 4; ++q) { cpa16(base + aS[q], gA + aO[q] + ko);
                                      cpa16(base + bS[q], gW + bO[q] + ko); }
        CPA_ARRIVE(smb + MB_OFF + st * 8);
    };

    prefetch(0);
    prefetch(1);

    #pragma unroll 1
    for (int ks = 0; ks < NKI; ++ks) {
        const int st = ks % 3;
        MBAR_WAIT(smb + MB_OFF + st * 8, (ks / 3) & 1);

        const uint32_t St = smb + st * STG_B;
        #pragma unroll
        for (int s = 0; s < 4; ++s) {
            uint32_t aF[4][4], bF[2][4];
            const uint32_t xA = (uint32_t)((2 * s + l4) << 4);
            const uint32_t xB = (uint32_t)((2 * s + l3) << 4);
            #pragma unroll
            for (int j2 = 0; j2 < 2; ++j2)
                LDM4(bF[j2], (St + basB[j2]) ^ xB);
            #pragma unroll
            for (int i = 0; i < 4; ++i)
                LDM4(aF[i], (St + basA[i]) ^ xA);
            #pragma unroll
            for (int i = 0; i < 4; ++i)
                #pragma unroll
                for (int j2 = 0; j2 < 2; ++j2) {
                    mma_f16(acc[i][2 * j2],     aF[i], &bF[j2][0]);
                    mma_f16(acc[i][2 * j2 + 1], aF[i], &bF[j2][2]);
                }
        }

        if (lane == 0) MBAR_ARRIVE(smb + MB_OFF + 24 + st * 8);

        const int kk = ks + 2;
        if (kk < NKI) {
            if (kk >= 3)
                MBAR_WAIT(smb + MB_OFF + 24 + (kk % 3) * 8, ((kk / 3) - 1) & 1);
            prefetch(kk);
        }
    }
    __syncthreads();

    // accums -> per-gate smem
    {
        const int sub = lane >> 2, kl = lane & 3;
        float* sgb = smf + wn * EPI_GS;
        #pragma unroll
        for (int i = 0; i < 4; ++i) {
            int rr = wm * 64 + i * 16 + sub;
            #pragma unroll
            for (int j = 0; j < 4; ++j) {
                int cc = j * 8 + 2 * kl;
                *reinterpret_cast<float2*>(&sgb[rr * 34 + cc]) =
                    make_float2(acc[i][j][0], acc[i][j][1]);
                *reinterpret_cast<float2*>(&sgb[(rr + 8) * 34 + cc]) =
                    make_float2(acc[i][j][2], acc[i][j][3]);
            }
        }
    }
    __syncthreads();

    {
        const int dloc = tid & 31, mb = tid >> 5;   // mb 0..7
        const float bI = smf[BIAS_FO + dloc];
        const float bF = smf[BIAS_FO + 32 + dloc];
        const float bO = smf[BIAS_FO + 64 + dloc];
        const float bZ = smf[BIAS_FO + 96 + dloc];
        const size_t PL = (size_t)BATCH * DIMC;
        #pragma unroll 4
        for (int rr = 0; rr < 16; ++rr) {
            int mm = rr * 8 + mb;
            size_t gx = (size_t)(m0 + mm) * DIMC + d0 + dloc;
            float it = smf[0 * EPI_GS + mm * 34 + dloc] + bI;
            float ft = smf[1 * EPI_GS + mm * 34 + dloc] + bF;
            float ot = smf[2 * EPI_GS + mm * 34 + dloc] + bO;
            float zt = smf[3 * EPI_GS + mm * 34 + dloc] + bZ;
            float cv = c_in[gx], nv = n_in[gx], mv = m_in[gx];
            float z  = tanhf(zt);
            float mn = fmaxf(ft + mv, it);
            float ei = __expf(it - mn);
            float ef = __expf(ft + mv - mn);
            float cn = ef * cv + ei * z;
            float nn2 = ef * nv + ei;
            float sgm = 1.0f / (1.0f + __expf(-ot));
            float hn = sgm * cn / (nn2 + 1e-6f);
            out[gx]          = hn;
            out[PL + gx]     = cn;
            out[2 * PL + gx] = nn2;
            out[3 * PL + gx] = mn;
        }
    }
}

extern "C" void kernel_launch(void* const* d_in, const int* in_sizes, int n_in_cnt,
                              void* d_out, int out_size)
{
    (void)in_sizes; (void)n_in_cnt; (void)out_size;
    const float* x  = (const float*)d_in[0];
    const float* h  = (const float*)d_in[1];
    const float* c  = (const float*)d_in[2];
    const float* nn = (const float*)d_in[3];
    const float* m  = (const float*)d_in[4];
    const float* Wi = (const float*)d_in[5];
    const float* bi = (const float*)d_in[6];
    const float* Wf = (const float*)d_in[7];
    const float* bf = (const float*)d_in[8];
    const float* Wo = (const float*)d_in[9];
    const float* bo = (const float*)d_in[10];
    const float* Wz = (const float*)d_in[11];
    const float* bz = (const float*)d_in[12];
    float* out = (float*)d_out;

    void* pA = nullptr; void* pW = nullptr;
    cudaGetSymbolAddress(&pA, g_Ah);
    cudaGetSymbolAddress(&pW, g_Wh);

    prep_A_kernel<<<16384, 256>>>(x, h);
    prep_W_kernel<<<16384, 256>>>(Wi, Wf, Wo, Wz);

    cudaFuncSetAttribute(slstm_gemm, cudaFuncAttributeMaxDynamicSharedMemorySize, SMEM_B);
    int grid = (BATCH / MT) * (DIMC / DT);   // 4096
    slstm_gemm<<<grid, 256, SMEM_B>>>((const __half*)pA, (const __half*)pW,
                                      c, nn, m, bi, bf, bo, bz, out);
}

// round 14
// speedup vs baseline: 1.6139x; 1.0218x over previous
#include <cuda_runtime.h>
#include <cuda.h>
#include <cuda_fp16.h>
#include <cstdint>
#include <cstdio>

#define BATCH 8192
#define DIMC  2048
#define KDIM  4096

#define MT 128
#define DT 32              // d-cols per gate per CTA; N_total = 128
#define KCH 64             // k halves per stage (128B rows)
#define NKI (KDIM / KCH)   // 64
#define STG_B 32768        // A 128*128B + B 128*128B
#define EPI_GS 4352        // floats per gate buffer (128*34)
#define BIAS_FO 24576      // float offset of bias (= 3*STG_B/4)
#define MB_OFF 98816       // byte offset of mbarriers (after bias)
#define SMEM_B 98880       // 3*STG_B + 512 + 64 (mbarriers)

__device__ __half g_Ah[(size_t)BATCH * KDIM];
__device__ __half g_Wh[(size_t)4 * DIMC * KDIM];

__device__ __forceinline__ uint32_t smem_u32(const void* p) {
    uint32_t a;
    asm("{ .reg .u64 t; cvta.to.shared.u64 t, %1; cvt.u32.u64 %0, t; }" : "=r"(a) : "l"(p));
    return a;
}
__device__ __forceinline__ void cpa16(uint32_t s, const void* g) {
    asm volatile("cp.async.cg.shared.global [%0], [%1], 16;" :: "r"(s), "l"(g) : "memory");
}
#define LDM4(r, a) \
    asm volatile("ldmatrix.sync.aligned.m8n8.x4.shared.b16 {%0,%1,%2,%3}, [%4];" \
        : "=r"((r)[0]), "=r"((r)[1]), "=r"((r)[2]), "=r"((r)[3]) : "r"(a))
__device__ __forceinline__ void mma_f16(float* d, const uint32_t* a, const uint32_t* b) {
    asm volatile(
        "mma.sync.aligned.m16n8k16.row.col.f32.f16.f16.f32 "
        "{%0,%1,%2,%3}, {%4,%5,%6,%7}, {%8,%9}, {%0,%1,%2,%3};"
        : "+f"(d[0]), "+f"(d[1]), "+f"(d[2]), "+f"(d[3])
        : "r"(a[0]), "r"(a[1]), "r"(a[2]), "r"(a[3]), "r"(b[0]), "r"(b[1]));
}
__device__ __forceinline__ uint32_t pack2(float a, float b) {
    __half2 h = __floats2half2_rn(a, b);
    return *reinterpret_cast<uint32_t*>(&h);
}

#define MBAR_INIT(a, c) \
    asm volatile("mbarrier.init.shared.b64 [%0], %1;" :: "r"((uint32_t)(a)), "r"((uint32_t)(c)) : "memory")
#define MBAR_ARRIVE(a) \
    asm volatile("mbarrier.arrive.shared.b64 _, [%0];" :: "r"((uint32_t)(a)) : "memory")
#define CPA_ARRIVE(a) \
    asm volatile("cp.async.mbarrier.arrive.noinc.shared.b64 [%0];" :: "r"((uint32_t)(a)) : "memory")
#define MBAR_WAIT(a, p) do { \
    uint32_t _mb = (uint32_t)(a), _pa = (uint32_t)(p), _dn; \
    asm volatile("{\n\t.reg .pred q;\n\tmbarrier.try_wait.parity.acquire.cta.shared::cta.b64 q, [%1], %2;\n\tselp.b32 %0,1,0,q;\n\t}" \
        : "=r"(_dn) : "r"(_mb), "r"(_pa) : "memory"); \
    if (!_dn) { \
        asm volatile("{\n\t.reg .pred Q;\n\tWL_%=:\n\tmbarrier.try_wait.parity.acquire.cta.shared::cta.b64 Q, [%0], %1, 0x989680;\n\t@Q bra.uni WD_%=;\n\tbra.uni WL_%=;\n\tWD_%=:\n\t}" \
            :: "r"(_mb), "r"(_pa) : "memory"); \
    } \
} while (0)

// ---- prep: f32 -> f16 RNE, plain k-order ----
__global__ void prep_A_kernel(const float* __restrict__ x, const float* __restrict__ h) {
    size_t idx = (size_t)blockIdx.x * blockDim.x + threadIdx.x;
    size_t row = idx >> 9; int seg = (int)(idx & 511);
    int cb = seg * 8;
    const float* src = (cb < 2048) ? (x + row * 2048 + cb) : (h + row * 2048 + (cb - 2048));
    float4 v0 = reinterpret_cast<const float4*>(src)[0];
    float4 v1 = reinterpret_cast<const float4*>(src)[1];
    reinterpret_cast<uint4*>(g_Ah)[idx] =
        make_uint4(pack2(v0.x, v0.y), pack2(v0.z, v0.w), pack2(v1.x, v1.y), pack2(v1.z, v1.w));
}
__global__ void prep_W_kernel(const float* __restrict__ wi, const float* __restrict__ wf,
                              const float* __restrict__ wo, const float* __restrict__ wz) {
    size_t idx = (size_t)blockIdx.x * blockDim.x + threadIdx.x;
    size_t j = idx >> 9; int seg = (int)(idx & 511);
    int gate = (int)(j >> 11); size_t r = j & 2047;
    const float* W = (gate == 0) ? wi : (gate == 1) ? wf : (gate == 2) ? wo : wz;
    const float* src = W + r * (size_t)KDIM + seg * 8;
    float4 v0 = reinterpret_cast<const float4*>(src)[0];
    float4 v1 = reinterpret_cast<const float4*>(src)[1];
    reinterpret_cast<uint4*>(g_Wh)[idx] =
        make_uint4(pack2(v0.x, v0.y), pack2(v0.z, v0.w), pack2(v1.x, v1.y), pack2(v1.z, v1.w));
}

// ---- fused GEMM (fp16 in, fp32 acc) + sLSTM; mbarrier-decoupled pipeline ----
__global__ void __launch_bounds__(256, 2)
slstm_gemm(const __half* __restrict__ gA, const __half* __restrict__ gW,
           const float* __restrict__ c_in, const float* __restrict__ n_in,
           const float* __restrict__ m_in,
           const float* __restrict__ bi, const float* __restrict__ bf_,
           const float* __restrict__ bo, const float* __restrict__ bz,
           float* __restrict__ out)
{
    extern __shared__ char smc[];
    float* smf = reinterpret_cast<float*>(smc);
    const int tid = threadIdx.x;
    const int lane = tid & 31, wid = tid >> 5;
    const int wm = wid & 1, wn = wid >> 1;     // M-half, gate

    int bid = blockIdx.x;
    int sg = bid >> 10, r_ = bid & 1023;
    int mt = (sg << 4) + (r_ & 15), dt = r_ >> 4;   // 16 m x 64 d per supergroup
    const int m0 = mt * MT, d0 = dt * DT;

    if (tid < 128) {
        int g = tid >> 5, jj = tid & 31;
        const float* bb = (g == 0) ? bi : (g == 1) ? bf_ : (g == 2) ? bo : bz;
        smf[BIAS_FO + tid] = bb[d0 + jj];
    }
    const uint32_t smb = smem_u32(smc);

    // mbarriers: full[3] at MB_OFF (count 256), free[3] at MB_OFF+24 (count 256, all lanes)
    if (tid < 3) {
        MBAR_INIT(smb + MB_OFF + tid * 8, 256);
        MBAR_INIT(smb + MB_OFF + 24 + tid * 8, 256);
    }

    // cp.async: A 1024 chunks (4/thr), B 1024 chunks (4/thr)
    uint32_t aS[4], aO[4], bS[4], bO[4];
    #pragma unroll
    for (int q = 0; q < 4; ++q) {
        int id = tid + q * 256, row = id >> 3, c = id & 7;
        aS[q] = (uint32_t)(row * 128 + ((c ^ (row & 7)) << 4));
        aO[q] = (uint32_t)((m0 + row) * KDIM + c * 8);
        int grow = ((row >> 5) << 11) + d0 + (row & 31);
        bS[q] = (uint32_t)(16384 + row * 128 + ((c ^ (row & 7)) << 4));
        bO[q] = (uint32_t)(grow * KDIM + c * 8);
    }

    // ldmatrix bases: addr = (St + bas) ^ (c<<4); swizzle XOR confined to bits [4:7)
    const int l7 = lane & 7, l3 = (lane >> 3) & 1, l4 = (lane >> 4) & 1;
    uint32_t basA[4], basB[2];
    #pragma unroll
    for (int i = 0; i < 4; ++i) {
        int ra = wm * 64 + i * 16 + l3 * 8 + l7;
        basA[i] = (uint32_t)(ra * 128 + ((ra & 7) << 4));
    }
    #pragma unroll
    for (int j2 = 0; j2 < 2; ++j2) {
        int rb = wn * 32 + j2 * 16 + l4 * 8 + l7;
        basB[j2] = (uint32_t)(16384 + rb * 128 + ((rb & 7) << 4));
    }

    float acc[4][4][4];
    #pragma unroll
    for (int i = 0; i < 4; ++i)
        #pragma unroll
        for (int j = 0; j < 4; ++j)
            #pragma unroll
            for (int t = 0; t < 4; ++t) acc[i][j][t] = 0.0f;

    __syncthreads();   // mbarrier init + bias visible before any cp.async/compute

    auto prefetch = [&](int kk) {
        int st = kk % 3;
        uint32_t base = smb + st * STG_B;
        int ko = kk * KCH;
        #pragma unroll
        for (int q = 0; q < 4; ++q) { cpa16(base + aS[q], gA + aO[q] + ko);
                                      cpa16(base + bS[q], gW + bO[q] + ko); }
        CPA_ARRIVE(smb + MB_OFF + st * 8);
    };

    prefetch(0);
    prefetch(1);

    #pragma unroll 1
    for (int ks = 0; ks < NKI; ++ks) {
        const int st = ks % 3;
        MBAR_WAIT(smb + MB_OFF + st * 8, (ks / 3) & 1);

        const uint32_t St = smb + st * STG_B;
        // substeps 0..2
        #pragma unroll
        for (int s = 0; s < 3; ++s) {
            uint32_t aF[4][4], bF[2][4];
            const uint32_t xA = (uint32_t)((2 * s + l4) << 4);
            const uint32_t xB = (uint32_t)((2 * s + l3) << 4);
            #pragma unroll
            for (int j2 = 0; j2 < 2; ++j2)
                LDM4(bF[j2], (St + basB[j2]) ^ xB);
            #pragma unroll
            for (int i = 0; i < 4; ++i)
                LDM4(aF[i], (St + basA[i]) ^ xA);
            #pragma unroll
            for (int i = 0; i < 4; ++i)
                #pragma unroll
                for (int j2 = 0; j2 < 2; ++j2) {
                    mma_f16(acc[i][2 * j2],     aF[i], &bF[j2][0]);
                    mma_f16(acc[i][2 * j2 + 1], aF[i], &bF[j2][2]);
                }
        }
        // substep 3: loads, then early stage release, then MMAs
        {
            uint32_t aF[4][4], bF[2][4];
            const uint32_t xA = (uint32_t)((6 + l4) << 4);
            const uint32_t xB = (uint32_t)((6 + l3) << 4);
            #pragma unroll
            for (int j2 = 0; j2 < 2; ++j2)
                LDM4(bF[j2], (St + basB[j2]) ^ xB);
            #pragma unroll
            for (int i = 0; i < 4; ++i)
                LDM4(aF[i], (St + basA[i]) ^ xA);
            MBAR_ARRIVE(smb + MB_OFF + 24 + st * 8);   // all lanes; stage readable no more
            #pragma unroll
            for (int i = 0; i < 4; ++i)
                #pragma unroll
                for (int j2 = 0; j2 < 2; ++j2) {
                    mma_f16(acc[i][2 * j2],     aF[i], &bF[j2][0]);
                    mma_f16(acc[i][2 * j2 + 1], aF[i], &bF[j2][2]);
                }
        }

        const int kk = ks + 2;
        if (kk < NKI) {
            if (kk >= 3)
                MBAR_WAIT(smb + MB_OFF + 24 + (kk % 3) * 8, ((kk / 3) - 1) & 1);
            prefetch(kk);
        }
    }
    __syncthreads();

    // accums -> per-gate smem
    {
        const int sub = lane >> 2, kl = lane & 3;
        float* sgb = smf + wn * EPI_GS;
        #pragma unroll
        for (int i = 0; i < 4; ++i) {
            int rr = wm * 64 + i * 16 + sub;
            #pragma unroll
            for (int j = 0; j < 4; ++j) {
                int cc = j * 8 + 2 * kl;
                *reinterpret_cast<float2*>(&sgb[rr * 34 + cc]) =
                    make_float2(acc[i][j][0], acc[i][j][1]);
                *reinterpret_cast<float2*>(&sgb[(rr + 8) * 34 + cc]) =
                    make_float2(acc[i][j][2], acc[i][j][3]);
            }
        }
    }
    __syncthreads();

    {
        const int dloc = tid & 31, mb = tid >> 5;   // mb 0..7
        const float bI = smf[BIAS_FO + dloc];
        const float bF = smf[BIAS_FO + 32 + dloc];
        const float bO = smf[BIAS_FO + 64 + dloc];
        const float bZ = smf[BIAS_FO + 96 + dloc];
        const size_t PL = (size_t)BATCH * DIMC;
        #pragma unroll 4
        for (int rr = 0; rr < 16; ++rr) {
            int mm = rr * 8 + mb;
            size_t gx = (size_t)(m0 + mm) * DIMC + d0 + dloc;
            float it = smf[0 * EPI_GS + mm * 34 + dloc] + bI;
            float ft = smf[1 * EPI_GS + mm * 34 + dloc] + bF;
            float ot = smf[2 * EPI_GS + mm * 34 + dloc] + bO;
            float zt = smf[3 * EPI_GS + mm * 34 + dloc] + bZ;
            float cv = c_in[gx], nv = n_in[gx], mv = m_in[gx];
            float z  = tanhf(zt);
            float mn = fmaxf(ft + mv, it);
            float ei = __expf(it - mn);
            float ef = __expf(ft + mv - mn);
            float cn = ef * cv + ei * z;
            float nn2 = ef * nv + ei;
            float sgm = 1.0f / (1.0f + __expf(-ot));
            float hn = sgm * cn / (nn2 + 1e-6f);
            out[gx]          = hn;
            out[PL + gx]     = cn;
            out[2 * PL + gx] = nn2;
            out[3 * PL + gx] = mn;
        }
    }
}

extern "C" void kernel_launch(void* const* d_in, const int* in_sizes, int n_in_cnt,
                              void* d_out, int out_size)
{
    (void)in_sizes; (void)n_in_cnt; (void)out_size;
    const float* x  = (const float*)d_in[0];
    const float* h  = (const float*)d_in[1];
    const float* c  = (const float*)d_in[2];
    const float* nn = (const float*)d_in[3];
    const float* m  = (const float*)d_in[4];
    const float* Wi = (const float*)d_in[5];
    const float* bi = (const float*)d_in[6];
    const float* Wf = (const float*)d_in[7];
    const float* bf = (const float*)d_in[8];
    const float* Wo = (const float*)d_in[9];
    const float* bo = (const float*)d_in[10];
    const float* Wz = (const float*)d_in[11];
    const float* bz = (const float*)d_in[12];
    float* out = (float*)d_out;

    void* pA = nullptr; void* pW = nullptr;
    cudaGetSymbolAddress(&pA, g_Ah);
    cudaGetSymbolAddress(&pW, g_Wh);

    prep_A_kernel<<<16384, 256>>>(x, h);
    prep_W_kernel<<<16384, 256>>>(Wi, Wf, Wo, Wz);

    cudaFuncSetAttribute(slstm_gemm, cudaFuncAttributeMaxDynamicSharedMemorySize, SMEM_B);
    int grid = (BATCH / MT) * (DIMC / DT);   // 4096
    slstm_gemm<<<grid, 256, SMEM_B>>>((const __half*)pA, (const __half*)pW,
                                      c, nn, m, bi, bf, bo, bz, out);
}

// round 15
// speedup vs baseline: 1.6416x; 1.0172x over previous
#include <cuda_runtime.h>
#include <cuda.h>
#include <cuda_fp16.h>
#include <cstdint>
#include <cstdio>

#define BATCH 8192
#define DIMC  2048
#define KDIM  4096

#define MT 128
#define DT 32              // d-cols per gate per CTA; N_total = 128
#define KCH 64             // k halves per stage (128B rows)
#define NKI (KDIM / KCH)   // 64
#define STG_B 32768        // A 128*128B + B 128*128B
#define EPI_GS 4352        // floats per gate buffer (128*34)
#define BIAS_FO 24576      // float offset of bias (= 3*STG_B/4)
#define MB_OFF 98816       // byte offset of mbarriers (after bias)
#define SMEM_B 98880       // 3*STG_B + 512 + 64 (mbarriers)

__device__ __half g_Ah[(size_t)BATCH * KDIM];
__device__ __half g_Wh[(size_t)4 * DIMC * KDIM];

__device__ __forceinline__ uint32_t smem_u32(const void* p) {
    uint32_t a;
    asm("{ .reg .u64 t; cvta.to.shared.u64 t, %1; cvt.u32.u64 %0, t; }" : "=r"(a) : "l"(p));
    return a;
}
__device__ __forceinline__ void cpa16(uint32_t s, const void* g) {
    asm volatile("cp.async.cg.shared.global [%0], [%1], 16;" :: "r"(s), "l"(g) : "memory");
}
#define LDM4(r, a) \
    asm volatile("ldmatrix.sync.aligned.m8n8.x4.shared.b16 {%0,%1,%2,%3}, [%4];" \
        : "=r"((r)[0]), "=r"((r)[1]), "=r"((r)[2]), "=r"((r)[3]) : "r"(a))
__device__ __forceinline__ void mma_f16(float* d, const uint32_t* a, const uint32_t* b) {
    asm volatile(
        "mma.sync.aligned.m16n8k16.row.col.f32.f16.f16.f32 "
        "{%0,%1,%2,%3}, {%4,%5,%6,%7}, {%8,%9}, {%0,%1,%2,%3};"
        : "+f"(d[0]), "+f"(d[1]), "+f"(d[2]), "+f"(d[3])
        : "r"(a[0]), "r"(a[1]), "r"(a[2]), "r"(a[3]), "r"(b[0]), "r"(b[1]));
}
__device__ __forceinline__ uint32_t pack2(float a, float b) {
    __half2 h = __floats2half2_rn(a, b);
    return *reinterpret_cast<uint32_t*>(&h);
}
__device__ __forceinline__ float tanh_fast(float x) {
    float r; asm("tanh.approx.f32 %0, %1;" : "=f"(r) : "f"(x));
    return r;
}

#define MBAR_INIT(a, c) \
    asm volatile("mbarrier.init.shared.b64 [%0], %1;" :: "r"((uint32_t)(a)), "r"((uint32_t)(c)) : "memory")
#define MBAR_ARRIVE(a) \
    asm volatile("mbarrier.arrive.shared.b64 _, [%0];" :: "r"((uint32_t)(a)) : "memory")
#define CPA_ARRIVE(a) \
    asm volatile("cp.async.mbarrier.arrive.noinc.shared.b64 [%0];" :: "r"((uint32_t)(a)) : "memory")
#define MBAR_WAIT(a, p) do { \
    uint32_t _mb = (uint32_t)(a), _pa = (uint32_t)(p), _dn; \
    asm volatile("{\n\t.reg .pred q;\n\tmbarrier.try_wait.parity.acquire.cta.shared::cta.b64 q, [%1], %2;\n\tselp.b32 %0,1,0,q;\n\t}" \
        : "=r"(_dn) : "r"(_mb), "r"(_pa) : "memory"); \
    if (!_dn) { \
        asm volatile("{\n\t.reg .pred Q;\n\tWL_%=:\n\tmbarrier.try_wait.parity.acquire.cta.shared::cta.b64 Q, [%0], %1, 0x989680;\n\t@Q bra.uni WD_%=;\n\tbra.uni WL_%=;\n\tWD_%=:\n\t}" \
            :: "r"(_mb), "r"(_pa) : "memory"); \
    } \
} while (0)

// ---- prep: f32 -> f16 RNE, plain k-order ----
__global__ void prep_A_kernel(const float* __restrict__ x, const float* __restrict__ h) {
    size_t idx = (size_t)blockIdx.x * blockDim.x + threadIdx.x;
    size_t row = idx >> 9; int seg = (int)(idx & 511);
    int cb = seg * 8;
    const float* src = (cb < 2048) ? (x + row * 2048 + cb) : (h + row * 2048 + (cb - 2048));
    float4 v0 = reinterpret_cast<const float4*>(src)[0];
    float4 v1 = reinterpret_cast<const float4*>(src)[1];
    reinterpret_cast<uint4*>(g_Ah)[idx] =
        make_uint4(pack2(v0.x, v0.y), pack2(v0.z, v0.w), pack2(v1.x, v1.y), pack2(v1.z, v1.w));
}
__global__ void prep_W_kernel(const float* __restrict__ wi, const float* __restrict__ wf,
                              const float* __restrict__ wo, const float* __restrict__ wz) {
    size_t idx = (size_t)blockIdx.x * blockDim.x + threadIdx.x;
    size_t j = idx >> 9; int seg = (int)(idx & 511);
    int gate = (int)(j >> 11); size_t r = j & 2047;
    const float* W = (gate == 0) ? wi : (gate == 1) ? wf : (gate == 2) ? wo : wz;
    const float* src = W + r * (size_t)KDIM + seg * 8;
    float4 v0 = reinterpret_cast<const float4*>(src)[0];
    float4 v1 = reinterpret_cast<const float4*>(src)[1];
    reinterpret_cast<uint4*>(g_Wh)[idx] =
        make_uint4(pack2(v0.x, v0.y), pack2(v0.z, v0.w), pack2(v1.x, v1.y), pack2(v1.z, v1.w));
}

// ---- fused GEMM (fp16 in, fp32 acc) + sLSTM; mbarrier-decoupled pipeline ----
__global__ void __launch_bounds__(256, 2)
slstm_gemm(const __half* __restrict__ gA, const __half* __restrict__ gW,
           const float* __restrict__ c_in, const float* __restrict__ n_in,
           const float* __restrict__ m_in,
           const float* __restrict__ bi, const float* __restrict__ bf_,
           const float* __restrict__ bo, const float* __restrict__ bz,
           float* __restrict__ out)
{
    extern __shared__ char smc[];
    float* smf = reinterpret_cast<float*>(smc);
    const int tid = threadIdx.x;
    const int lane = tid & 31, wid = tid >> 5;
    const int wm = wid & 1, wn = wid >> 1;     // M-half, gate

    int bid = blockIdx.x;
    int sg = bid >> 10, r_ = bid & 1023;
    int mt = (sg << 4) + (r_ & 15), dt = r_ >> 4;   // 16 m x 64 d per supergroup
    const int m0 = mt * MT, d0 = dt * DT;

    if (tid < 128) {
        int g = tid >> 5, jj = tid & 31;
        const float* bb = (g == 0) ? bi : (g == 1) ? bf_ : (g == 2) ? bo : bz;
        smf[BIAS_FO + tid] = bb[d0 + jj];
    }
    const uint32_t smb = smem_u32(smc);

    // mbarriers: full[3] at MB_OFF (count 256), free[3] at MB_OFF+24 (count 256, all lanes)
    if (tid < 3) {
        MBAR_INIT(smb + MB_OFF + tid * 8, 256);
        MBAR_INIT(smb + MB_OFF + 24 + tid * 8, 256);
    }

    // cp.async: A 1024 chunks (4/thr), B 1024 chunks (4/thr)
    uint32_t aS[4], aO[4], bS[4], bO[4];
    #pragma unroll
    for (int q = 0; q < 4; ++q) {
        int id = tid + q * 256, row = id >> 3, c = id & 7;
        aS[q] = (uint32_t)(row * 128 + ((c ^ (row & 7)) << 4));
        aO[q] = (uint32_t)((m0 + row) * KDIM + c * 8);
        int grow = ((row >> 5) << 11) + d0 + (row & 31);
        bS[q] = (uint32_t)(16384 + row * 128 + ((c ^ (row & 7)) << 4));
        bO[q] = (uint32_t)(grow * KDIM + c * 8);
    }

    // ldmatrix bases: addr = (St + bas) ^ (c<<4); swizzle XOR confined to bits [4:7)
    const int l7 = lane & 7, l3 = (lane >> 3) & 1, l4 = (lane >> 4) & 1;
    uint32_t basA[4], basB[2];
    #pragma unroll
    for (int i = 0; i < 4; ++i) {
        int ra = wm * 64 + i * 16 + l3 * 8 + l7;
        basA[i] = (uint32_t)(ra * 128 + ((ra & 7) << 4));
    }
    #pragma unroll
    for (int j2 = 0; j2 < 2; ++j2) {
        int rb = wn * 32 + j2 * 16 + l4 * 8 + l7;
        basB[j2] = (uint32_t)(16384 + rb * 128 + ((rb & 7) << 4));
    }

    float acc[4][4][4];
    #pragma unroll
    for (int i = 0; i < 4; ++i)
        #pragma unroll
        for (int j = 0; j < 4; ++j)
            #pragma unroll
            for (int t = 0; t < 4; ++t) acc[i][j][t] = 0.0f;

    __syncthreads();   // mbarrier init + bias visible before any cp.async/compute

    auto prefetch = [&](int kk) {
        int st = kk % 3;
        uint32_t base = smb + st * STG_B;
        int ko = kk * KCH;
        #pragma unroll
        for (int q = 0; q < 4; ++q) { cpa16(base + aS[q], gA + aO[q] + ko);
                                      cpa16(base + bS[q], gW + bO[q] + ko); }
        CPA_ARRIVE(smb + MB_OFF + st * 8);
    };

    prefetch(0);
    prefetch(1);

    #pragma unroll 1
    for (int ks = 0; ks < NKI; ++ks) {
        const int st = ks % 3;
        MBAR_WAIT(smb + MB_OFF + st * 8, (ks / 3) & 1);

        const uint32_t St = smb + st * STG_B;
        // substeps 0..2
        #pragma unroll
        for (int s = 0; s < 3; ++s) {
            uint32_t aF[4][4], bF[2][4];
            const uint32_t xA = (uint32_t)((2 * s + l4) << 4);
            const uint32_t xB = (uint32_t)((2 * s + l3) << 4);
            #pragma unroll
            for (int j2 = 0; j2 < 2; ++j2)
                LDM4(bF[j2], (St + basB[j2]) ^ xB);
            #pragma unroll
            for (int i = 0; i < 4; ++i)
                LDM4(aF[i], (St + basA[i]) ^ xA);
            #pragma unroll
            for (int i = 0; i < 4; ++i)
                #pragma unroll
                for (int j2 = 0; j2 < 2; ++j2) {
                    mma_f16(acc[i][2 * j2],     aF[i], &bF[j2][0]);
                    mma_f16(acc[i][2 * j2 + 1], aF[i], &bF[j2][2]);
                }
        }
        // substep 3: loads, then early stage release, then MMAs
        {
            uint32_t aF[4][4], bF[2][4];
            const uint32_t xA = (uint32_t)((6 + l4) << 4);
            const uint32_t xB = (uint32_t)((6 + l3) << 4);
            #pragma unroll
            for (int j2 = 0; j2 < 2; ++j2)
                LDM4(bF[j2], (St + basB[j2]) ^ xB);
            #pragma unroll
            for (int i = 0; i < 4; ++i)
                LDM4(aF[i], (St + basA[i]) ^ xA);
            MBAR_ARRIVE(smb + MB_OFF + 24 + st * 8);   // all lanes; stage readable no more
            #pragma unroll
            for (int i = 0; i < 4; ++i)
                #pragma unroll
                for (int j2 = 0; j2 < 2; ++j2) {
                    mma_f16(acc[i][2 * j2],     aF[i], &bF[j2][0]);
                    mma_f16(acc[i][2 * j2 + 1], aF[i], &bF[j2][2]);
                }
        }

        const int kk = ks + 2;
        if (kk < NKI) {
            if (kk >= 3)
                MBAR_WAIT(smb + MB_OFF + 24 + (kk % 3) * 8, ((kk / 3) - 1) & 1);
            prefetch(kk);
        }
    }
    __syncthreads();

    // accums -> per-gate smem
    {
        const int sub = lane >> 2, kl = lane & 3;
        float* sgb = smf + wn * EPI_GS;
        #pragma unroll
        for (int i = 0; i < 4; ++i) {
            int rr = wm * 64 + i * 16 + sub;
            #pragma unroll
            for (int j = 0; j < 4; ++j) {
                int cc = j * 8 + 2 * kl;
                *reinterpret_cast<float2*>(&sgb[rr * 34 + cc]) =
                    make_float2(acc[i][j][0], acc[i][j][1]);
                *reinterpret_cast<float2*>(&sgb[(rr + 8) * 34 + cc]) =
                    make_float2(acc[i][j][2], acc[i][j][3]);
            }
        }
    }
    __syncthreads();

    {
        const int dloc = tid & 31, mb = tid >> 5;   // mb 0..7
        const float bI = smf[BIAS_FO + dloc];
        const float bF = smf[BIAS_FO + 32 + dloc];
        const float bO = smf[BIAS_FO + 64 + dloc];
        const float bZ = smf[BIAS_FO + 96 + dloc];
        const size_t PL = (size_t)BATCH * DIMC;
        #pragma unroll 4
        for (int rr = 0; rr < 16; ++rr) {
            int mm = rr * 8 + mb;
            size_t gx = (size_t)(m0 + mm) * DIMC + d0 + dloc;
            float it = smf[0 * EPI_GS + mm * 34 + dloc] + bI;
            float ft = smf[1 * EPI_GS + mm * 34 + dloc] + bF;
            float ot = smf[2 * EPI_GS + mm * 34 + dloc] + bO;
            float zt = smf[3 * EPI_GS + mm * 34 + dloc] + bZ;
            float cv = c_in[gx], nv = n_in[gx], mv = m_in[gx];
            float z  = tanh_fast(zt);
            float mn = fmaxf(ft + mv, it);
            float ei = __expf(it - mn);
            float ef = __expf(ft + mv - mn);
            float cn = ef * cv + ei * z;
            float nn2 = ef * nv + ei;
            float sgm = 0.5f + 0.5f * tanh_fast(0.5f * ot);
            float hn = __fdividef(sgm * cn, nn2 + 1e-6f);
            out[gx]          = hn;
            out[PL + gx]     = cn;
            out[2 * PL + gx] = nn2;
            out[3 * PL + gx] = mn;
        }
    }
}

extern "C" void kernel_launch(void* const* d_in, const int* in_sizes, int n_in_cnt,
                              void* d_out, int out_size)
{
    (void)in_sizes; (void)n_in_cnt; (void)out_size;
    const float* x  = (const float*)d_in[0];
    const float* h  = (const float*)d_in[1];
    const float* c  = (const float*)d_in[2];
    const float* nn = (const float*)d_in[3];
    const float* m  = (const float*)d_in[4];
    const float* Wi = (const float*)d_in[5];
    const float* bi = (const float*)d_in[6];
    const float* Wf = (const float*)d_in[7];
    const float* bf = (const float*)d_in[8];
    const float* Wo = (const float*)d_in[9];
    const float* bo = (const float*)d_in[10];
    const float* Wz = (const float*)d_in[11];
    const float* bz = (const float*)d_in[12];
    float* out = (float*)d_out;

    void* pA = nullptr; void* pW = nullptr;
    cudaGetSymbolAddress(&pA, g_Ah);
    cudaGetSymbolAddress(&pW, g_Wh);

    prep_A_kernel<<<16384, 256>>>(x, h);
    prep_W_kernel<<<16384, 256>>>(Wi, Wf, Wo, Wz);

    cudaFuncSetAttribute(slstm_gemm, cudaFuncAttributeMaxDynamicSharedMemorySize, SMEM_B);
    int grid = (BATCH / MT) * (DIMC / DT);   // 4096
    slstm_gemm<<<grid, 256, SMEM_B>>>((const __half*)pA, (const __half*)pW,
                                      c, nn, m, bi, bf, bo, bz, out);
}